// round 8
// baseline (speedup 1.0000x reference)
#include <cuda_runtime.h>
#include <cstdint>

// Problem constants
constexpr int kB = 4;
constexpr int kN = 1024;
constexpr int kD = 256;
constexpr int kH = 8;
constexpr int kDH  = kD * kH;          // 2048
constexpr int kNDH = kN * kDH;         // 2097152
constexpr int kSeg = kB * kNDH;        // 8388608  (q/k/v segment, floats)
constexpr int kC3  = 3 * kDH;          // 6144
constexpr int kRows = kB * kN;         // 4096

// Scratch (device globals; no dynamic allocation allowed)
__device__ float g_qkv[3ull * kSeg];   // ~100.7 MB : QKV in reference flat layout
__device__ float g_qkT[2ull * kSeg];   // ~64 MB : q(pre-scaled),k transposed [seg][bh][n][qd]
__device__ float g_diag[kRows * kH];
__device__ float g_part4[4][kRows * kD];  // k3 K-split partials (64 MB)

// ---------------- cp.async helpers ----------------
__device__ __forceinline__ void cp16(void* smem_dst, const void* gmem_src) {
    unsigned s = (unsigned)__cvta_generic_to_shared(smem_dst);
    asm volatile("cp.async.cg.shared.global [%0], [%1], 16;\n" :: "r"(s), "l"(gmem_src));
}
__device__ __forceinline__ void cp_commit() {
    asm volatile("cp.async.commit_group;\n");
}
template <int N>
__device__ __forceinline__ void cp_wait() {
    asm volatile("cp.async.wait_group %0;\n" :: "n"(N));
}

// ---------------------------------------------------------------------------
// Kernel 1: QKV = x @ Wqkv + bqkv     [4096,256] @ [256,6144]
// (round-2 proven version, verbatim)
// ---------------------------------------------------------------------------
__global__ __launch_bounds__(256, 2)
void qkv_gemm_kernel(const float* __restrict__ x,
                     const float* __restrict__ W,
                     const float* __restrict__ bias)
{
    extern __shared__ float sm[];
    float* As = sm;                    // [2][128][36]
    float* Bs = sm + 2 * 128 * 36;     // [2][32][132]

    const int t  = threadIdx.x;
    const int tx = t & 15, ty = t >> 4;
    const int r0 = blockIdx.y * 128;
    const int c0 = blockIdx.x * 128;

    const int af = t & 7,  am = t >> 3;
    const int bc = t & 31, bk = t >> 5;

    float acc[8][8];
#pragma unroll
    for (int i = 0; i < 8; i++)
#pragma unroll
        for (int j = 0; j < 8; j++) acc[i][j] = 0.f;

#pragma unroll
    for (int i = 0; i < 4; i++) {
        int m = am + i * 32;
        cp16(&As[m * 36 + af * 4], &x[(size_t)(r0 + m) * kD + af * 4]);
    }
#pragma unroll
    for (int i = 0; i < 4; i++) {
        int k = bk + i * 8;
        cp16(&Bs[k * 132 + bc * 4], &W[(size_t)k * kC3 + c0 + bc * 4]);
    }
    cp_commit();

    for (int c = 0; c < 8; c++) {
        const int buf = c & 1;
        if (c < 7) {
            const int kc = (c + 1) * 32;
            const int nb = buf ^ 1;
#pragma unroll
            for (int i = 0; i < 4; i++) {
                int m = am + i * 32;
                cp16(&As[nb * 128 * 36 + m * 36 + af * 4],
                     &x[(size_t)(r0 + m) * kD + kc + af * 4]);
            }
#pragma unroll
            for (int i = 0; i < 4; i++) {
                int k = bk + i * 8;
                cp16(&Bs[nb * 32 * 132 + k * 132 + bc * 4],
                     &W[(size_t)(kc + k) * kC3 + c0 + bc * 4]);
            }
            cp_commit();
            cp_wait<1>();
        } else {
            cp_wait<0>();
        }
        __syncthreads();

        const float* A_ = &As[buf * 128 * 36];
        const float* B_ = &Bs[buf * 32 * 132];
#pragma unroll
        for (int kg = 0; kg < 32; kg += 4) {
            float4 av[8];
#pragma unroll
            for (int gi = 0; gi < 2; gi++)
#pragma unroll
                for (int i = 0; i < 4; i++)
                    av[gi * 4 + i] =
                        *(const float4*)&A_[(gi * 64 + ty * 4 + i) * 36 + kg];
#pragma unroll
            for (int kk = 0; kk < 4; kk++) {
                float4 b0 = *(const float4*)&B_[(kg + kk) * 132 + tx * 4];
                float4 b1 = *(const float4*)&B_[(kg + kk) * 132 + tx * 4 + 64];
#pragma unroll
                for (int r = 0; r < 8; r++) {
                    float a = (kk == 0) ? av[r].x : (kk == 1) ? av[r].y
                             : (kk == 2) ? av[r].z : av[r].w;
                    acc[r][0] = fmaf(a, b0.x, acc[r][0]);
                    acc[r][1] = fmaf(a, b0.y, acc[r][1]);
                    acc[r][2] = fmaf(a, b0.z, acc[r][2]);
                    acc[r][3] = fmaf(a, b0.w, acc[r][3]);
                    acc[r][4] = fmaf(a, b1.x, acc[r][4]);
                    acc[r][5] = fmaf(a, b1.y, acc[r][5]);
                    acc[r][6] = fmaf(a, b1.z, acc[r][6]);
                    acc[r][7] = fmaf(a, b1.w, acc[r][7]);
                }
            }
        }
        __syncthreads();
    }

#pragma unroll
    for (int gi = 0; gi < 2; gi++)
#pragma unroll
        for (int i = 0; i < 4; i++) {
            int r  = r0 + gi * 64 + ty * 4 + i;
            int rr = gi * 4 + i;
#pragma unroll
            for (int gj = 0; gj < 2; gj++) {
                int c = c0 + gj * 64 + tx * 4;
                float4 v;
                v.x = acc[rr][gj * 4 + 0] + bias[c + 0];
                v.y = acc[rr][gj * 4 + 1] + bias[c + 1];
                v.z = acc[rr][gj * 4 + 2] + bias[c + 2];
                v.w = acc[rr][gj * 4 + 3] + bias[c + 3];
                *(float4*)&g_qkv[(size_t)r * kC3 + c] = v;
            }
        }
}

// ---------------------------------------------------------------------------
// Transpose: q,k segments -> g_qkT[seg][b][h][n][qd]; q scaled by 1/16 here
// so kernel 2's scores need no epilogue scaling.
// ---------------------------------------------------------------------------
__global__ __launch_bounds__(256)
void transpose_qk_kernel()
{
    __shared__ float smt[8][32][33];   // [h][qd][n]
    const int bid = blockIdx.x;
    const int qb  = bid & 7;
    const int nb  = (bid >> 3) & 31;
    const int b   = (bid >> 8) & 3;
    const int seg = bid >> 10;
    const int t   = threadIdx.x;
    const float sc = (seg == 0) ? 0.0625f : 1.0f;

    const float* src = g_qkv + (size_t)seg * kSeg + (size_t)b * kNDH
                     + (size_t)(nb * 32) * kDH + qb * 32 * 8;
    {
        const int nl = t >> 3, f = t & 7;
        const int h0 = (f & 1) * 4, q0 = f >> 1;
#pragma unroll
        for (int i = 0; i < 8; i++) {
            float4 v = *(const float4*)&src[(size_t)nl * kDH + (f + i * 8) * 4];
            int ql = q0 + i * 4;
            smt[h0 + 0][ql][nl] = v.x;
            smt[h0 + 1][ql][nl] = v.y;
            smt[h0 + 2][ql][nl] = v.z;
            smt[h0 + 3][ql][nl] = v.w;
        }
    }
    __syncthreads();
    {
        const int q4 = (t & 7) * 4, hn = t >> 3;
#pragma unroll
        for (int i = 0; i < 8; i++) {
            int idx = hn + i * 32;
            int h = idx >> 5, n = idx & 31;
            float4 v;
            v.x = smt[h][q4 + 0][n] * sc;
            v.y = smt[h][q4 + 1][n] * sc;
            v.z = smt[h][q4 + 2][n] * sc;
            v.w = smt[h][q4 + 3][n] * sc;
            float* dst = g_qkT + (size_t)seg * kSeg
                       + (((size_t)(b * 8 + h) * kN + nb * 32 + n) * kD)
                       + qb * 32 + q4;
            *(float4*)dst = v;
        }
    }
}

// ---------------------------------------------------------------------------
// Kernel 2: per (b,h): S[m,n] = qs_m . k_n (q pre-scaled); column softmax
// over m; keep diagonal attn only.
// No max pass (|S| <~ 1 by construction: std(S)~0.1, exp never overflows).
// Per-thread register colsum over ALL m-tiles; ONE final reduction.
// CTA: 128 n-cols, m swept in 8 tiles of 128. 256 threads, 8x8 microtile.
// ---------------------------------------------------------------------------
__global__ __launch_bounds__(256, 2)
void score_diag_kernel()
{
    extern __shared__ float sm[];
    float* As  = sm;                       // [2][128*36]
    float* Ks  = sm + 2 * 4608;            // [2][32*132]
    float* red = sm + 2 * 4608 + 2 * 4224; // [16*128]

    const int t  = threadIdx.x;
    const int tx = t & 15, ty = t >> 4;
    const int bh = blockIdx.y;
    const int b  = bh >> 3, h = bh & 7;
    const int n0 = blockIdx.x * 128;

    const float* Q  = g_qkT + (size_t)bh * (kN * kD);
    const float* Kp = g_qkT + (size_t)kSeg + (size_t)bh * (kN * kD);

    const int af = t & 7, am = t >> 3;   // A loader
    const int kq = t & 7, nl = t >> 3;   // K loader

    float colsum[8], dexp[8];
#pragma unroll
    for (int j = 0; j < 8; j++) { colsum[j] = 0.f; dexp[j] = 0.f; }

    for (int mt = 0; mt < 8; mt++) {
        const int m0 = mt * 128;
        float acc[8][8];
#pragma unroll
        for (int i = 0; i < 8; i++)
#pragma unroll
            for (int j = 0; j < 8; j++) acc[i][j] = 0.f;

        // preload chunk 0: A via cp.async, K into regs
        float4 kreg[4];
#pragma unroll
        for (int i = 0; i < 4; i++) {
            int m = am + i * 32;
            cp16(&As[m * 36 + af * 4], &Q[(size_t)(m0 + m) * kD + af * 4]);
        }
#pragma unroll
        for (int i = 0; i < 4; i++)
            kreg[i] = *(const float4*)&Kp[(size_t)(n0 + nl + 32 * i) * kD + kq * 4];
        cp_commit();

        for (int c = 0; c < 8; c++) {
            const int buf = c & 1;
            {
                float* kb_ = &Ks[buf * 4224];
#pragma unroll
                for (int i = 0; i < 4; i++) {
                    int n = nl + 32 * i;
                    kb_[(kq * 4 + 0) * 132 + n] = kreg[i].x;
                    kb_[(kq * 4 + 1) * 132 + n] = kreg[i].y;
                    kb_[(kq * 4 + 2) * 132 + n] = kreg[i].z;
                    kb_[(kq * 4 + 3) * 132 + n] = kreg[i].w;
                }
            }
            if (c < 7) {
                const int kc = (c + 1) * 32;
#pragma unroll
                for (int i = 0; i < 4; i++) {
                    int m = am + i * 32;
                    cp16(&As[(buf ^ 1) * 4608 + m * 36 + af * 4],
                         &Q[(size_t)(m0 + m) * kD + kc + af * 4]);
                }
                cp_commit();
#pragma unroll
                for (int i = 0; i < 4; i++)
                    kreg[i] = *(const float4*)
                        &Kp[(size_t)(n0 + nl + 32 * i) * kD + kc + kq * 4];
                cp_wait<1>();
            } else {
                cp_wait<0>();
            }
            __syncthreads();

            const float* A_ = &As[buf * 4608];
            const float* K_ = &Ks[buf * 4224];
#pragma unroll
            for (int kg = 0; kg < 32; kg += 4) {
                float4 av[8];
#pragma unroll
                for (int gi = 0; gi < 2; gi++)
#pragma unroll
                    for (int i = 0; i < 4; i++)
                        av[gi * 4 + i] =
                            *(const float4*)&A_[(gi * 64 + ty * 4 + i) * 36 + kg];
#pragma unroll
                for (int kk = 0; kk < 4; kk++) {
                    float4 b0v = *(const float4*)&K_[(kg + kk) * 132 + tx * 4];
                    float4 b1v = *(const float4*)&K_[(kg + kk) * 132 + tx * 4 + 64];
#pragma unroll
                    for (int r = 0; r < 8; r++) {
                        float a = (kk == 0) ? av[r].x : (kk == 1) ? av[r].y
                                 : (kk == 2) ? av[r].z : av[r].w;
                        acc[r][0] = fmaf(a, b0v.x, acc[r][0]);
                        acc[r][1] = fmaf(a, b0v.y, acc[r][1]);
                        acc[r][2] = fmaf(a, b0v.z, acc[r][2]);
                        acc[r][3] = fmaf(a, b0v.w, acc[r][3]);
                        acc[r][4] = fmaf(a, b1v.x, acc[r][4]);
                        acc[r][5] = fmaf(a, b1v.y, acc[r][5]);
                        acc[r][6] = fmaf(a, b1v.z, acc[r][6]);
                        acc[r][7] = fmaf(a, b1v.w, acc[r][7]);
                    }
                }
            }
            __syncthreads();
        }

        // ---- register-only epilogue: no barriers, no smem ----
        // diagonal: global m == global n  <=>  mt == blockIdx.x, tx == ty, r == j
        if (mt == blockIdx.x && tx == ty) {
#pragma unroll
            for (int j = 0; j < 8; j++) dexp[j] = __expf(acc[j][j]);
        }
#pragma unroll
        for (int jj = 0; jj < 8; jj++) {
            float s = colsum[jj];
#pragma unroll
            for (int r = 0; r < 8; r++) s += __expf(acc[r][jj]);
            colsum[jj] = s;
        }
    }

    // ---- single final reduction across the 16 ty-groups ----
#pragma unroll
    for (int jj = 0; jj < 8; jj++) {
        int cl = (jj >> 2) * 64 + tx * 4 + (jj & 3);
        red[ty * 128 + cl] = colsum[jj];
    }
    __syncthreads();
    float total = 0.f;
    if (t < 128) {
        total = red[t];
#pragma unroll
        for (int r = 1; r < 16; r++) total += red[r * 128 + t];
    }
    __syncthreads();
#pragma unroll
    for (int jj = 0; jj < 8; jj++) {
        int cl = (jj >> 2) * 64 + tx * 4 + (jj & 3);
        red[ty * 128 + cl] = dexp[jj];
    }
    __syncthreads();
    if (t < 128) {
        float dv = red[t];
#pragma unroll
        for (int r = 1; r < 16; r++) dv += red[r * 128 + t];
        g_diag[((size_t)b * kN + (n0 + t)) * kH + h] = dv / total;
    }
}

// ---------------------------------------------------------------------------
// Kernel 3: partial = (diag .* v) @ W0, K-split 4.  [4096,2048]@[2048,256]
// k1's proven 8x8/128x128 structure; A = diag*v fused in staging (LDG+STS),
// W0 staged k-major via direct cp.async (it's [K][N] row-major).
// grid(2 ctiles, 32 mtiles, 4 ksplit) = 256 CTAs.
// ---------------------------------------------------------------------------
__global__ __launch_bounds__(256, 2)
void out_gemm_kernel(const float* __restrict__ W0)
{
    extern __shared__ float sm[];
    float* As  = sm;                    // [2][128*36]
    float* Ws  = sm + 2 * 4608;         // [2][32*132]
    float* dsm = sm + 2 * 4608 + 2 * 4224;  // [128*8]

    const int t  = threadIdx.x;
    const int tx = t & 15, ty = t >> 4;
    const int c0 = blockIdx.x * 128;
    const int r0 = blockIdx.y * 128;
    const int kb = blockIdx.z * 512;
    const float* vseg = g_qkv + 2ull * kSeg;
    float* dst = g_part4[blockIdx.z];

    for (int idx = t; idx < 1024; idx += 256)
        dsm[idx] = g_diag[(size_t)(r0 + (idx >> 3)) * kH + (idx & 7)];

    const int af = t & 7,  am = t >> 3;   // A: f4 k-col af, rows am+32i
    const int bc = t & 31, bk = t >> 5;   // W: f4 col bc, k rows bk+8i

    float acc[8][8];
#pragma unroll
    for (int i = 0; i < 8; i++)
#pragma unroll
        for (int j = 0; j < 8; j++) acc[i][j] = 0.f;

    // preload chunk 0
    float4 areg[4];
#pragma unroll
    for (int i = 0; i < 4; i++) {
        int k = bk + i * 8;
        cp16(&Ws[k * 132 + bc * 4], &W0[(size_t)(kb + k) * kD + c0 + bc * 4]);
    }
    cp_commit();
#pragma unroll
    for (int i = 0; i < 4; i++) {
        int m = am + 32 * i;
        areg[i] = *(const float4*)&vseg[(size_t)(r0 + m) * kDH + kb + af * 4];
    }
    __syncthreads();   // dsm ready

    for (int c = 0; c < 16; c++) {
        const int buf = c & 1;
        {
            const int hoff = (af * 4) & 4;
#pragma unroll
            for (int i = 0; i < 4; i++) {
                int m = am + 32 * i;
                float4 dv = *(const float4*)&dsm[m * 8 + hoff];
                float4 v = areg[i];
                v.x *= dv.x; v.y *= dv.y; v.z *= dv.z; v.w *= dv.w;
                *(float4*)&As[buf * 4608 + m * 36 + af * 4] = v;
            }
        }
        if (c < 15) {
            const int kc = (c + 1) * 32;
#pragma unroll
            for (int i = 0; i < 4; i++) {
                int k = bk + i * 8;
                cp16(&Ws[(buf ^ 1) * 4224 + k * 132 + bc * 4],
                     &W0[(size_t)(kb + kc + k) * kD + c0 + bc * 4]);
            }
            cp_commit();
#pragma unroll
            for (int i = 0; i < 4; i++) {
                int m = am + 32 * i;
                areg[i] = *(const float4*)
                    &vseg[(size_t)(r0 + m) * kDH + kb + kc + af * 4];
            }
            cp_wait<1>();
        } else {
            cp_wait<0>();
        }
        __syncthreads();

        const float* A_ = &As[buf * 4608];
        const float* W_ = &Ws[buf * 4224];
#pragma unroll
        for (int kg = 0; kg < 32; kg += 4) {
            float4 av[8];
#pragma unroll
            for (int gi = 0; gi < 2; gi++)
#pragma unroll
                for (int i = 0; i < 4; i++)
                    av[gi * 4 + i] =
                        *(const float4*)&A_[(gi * 64 + ty * 4 + i) * 36 + kg];
#pragma unroll
            for (int kk = 0; kk < 4; kk++) {
                float4 b0v = *(const float4*)&W_[(kg + kk) * 132 + tx * 4];
                float4 b1v = *(const float4*)&W_[(kg + kk) * 132 + tx * 4 + 64];
#pragma unroll
                for (int r = 0; r < 8; r++) {
                    float a = (kk == 0) ? av[r].x : (kk == 1) ? av[r].y
                             : (kk == 2) ? av[r].z : av[r].w;
                    acc[r][0] = fmaf(a, b0v.x, acc[r][0]);
                    acc[r][1] = fmaf(a, b0v.y, acc[r][1]);
                    acc[r][2] = fmaf(a, b0v.z, acc[r][2]);
                    acc[r][3] = fmaf(a, b0v.w, acc[r][3]);
                    acc[r][4] = fmaf(a, b1v.x, acc[r][4]);
                    acc[r][5] = fmaf(a, b1v.y, acc[r][5]);
                    acc[r][6] = fmaf(a, b1v.z, acc[r][6]);
                    acc[r][7] = fmaf(a, b1v.w, acc[r][7]);
                }
            }
        }
        __syncthreads();
    }

#pragma unroll
    for (int gi = 0; gi < 2; gi++)
#pragma unroll
        for (int i = 0; i < 4; i++) {
            int r  = r0 + gi * 64 + ty * 4 + i;
            int rr = gi * 4 + i;
#pragma unroll
            for (int gj = 0; gj < 2; gj++) {
                int c = c0 + gj * 64 + tx * 4;
                float4 v;
                v.x = acc[rr][gj * 4 + 0];
                v.y = acc[rr][gj * 4 + 1];
                v.z = acc[rr][gj * 4 + 2];
                v.w = acc[rr][gj * 4 + 3];
                *(float4*)&dst[(size_t)r * kD + c] = v;
            }
        }
}

// ---------------------------------------------------------------------------
// Kernel 3b: out = sum of 4 partials + b0
// ---------------------------------------------------------------------------
__global__ __launch_bounds__(256)
void out_combine(const float* __restrict__ b0, float* __restrict__ out)
{
    int i4 = blockIdx.x * 256 + threadIdx.x;     // float4 index, 262144 total
    float4 a = *(const float4*)&g_part4[0][(size_t)i4 * 4];
    float4 b = *(const float4*)&g_part4[1][(size_t)i4 * 4];
    float4 c = *(const float4*)&g_part4[2][(size_t)i4 * 4];
    float4 d = *(const float4*)&g_part4[3][(size_t)i4 * 4];
    float4 bb = *(const float4*)&b0[(i4 & 63) * 4];
    float4 v;
    v.x = a.x + b.x + c.x + d.x + bb.x;
    v.y = a.y + b.y + c.y + d.y + bb.y;
    v.z = a.z + b.z + c.z + d.z + bb.z;
    v.w = a.w + b.w + c.w + d.w + bb.w;
    *(float4*)&out[(size_t)i4 * 4] = v;
}

// ---------------------------------------------------------------------------
extern "C" void kernel_launch(void* const* d_in, const int* in_sizes, int n_in,
                              void* d_out, int out_size)
{
    const float *x = nullptr, *Wqkv = nullptr, *bqkv = nullptr,
                *W0 = nullptr, *b0 = nullptr;
    for (int i = 0; i < n_in; i++) {
        switch (in_sizes[i]) {
            case kRows * kD: x    = (const float*)d_in[i]; break;
            case kD * kC3:   Wqkv = (const float*)d_in[i]; break;
            case kC3:        bqkv = (const float*)d_in[i]; break;
            case kDH * kD:   W0   = (const float*)d_in[i]; break;
            case kD:         b0   = (const float*)d_in[i]; break;
            default: break;
        }
    }
    float* out = (float*)d_out;

    const size_t smem1 = (size_t)(2 * 4608 + 2 * 4224) * sizeof(float);          // 70656
    const size_t smem2 = (size_t)(2 * 4608 + 2 * 4224 + 2048) * sizeof(float);   // 78848
    const size_t smem3 = (size_t)(2 * 4608 + 2 * 4224 + 1024) * sizeof(float);   // 74752
    static bool attr_done = false;
    if (!attr_done) {
        cudaFuncSetAttribute(qkv_gemm_kernel,
                             cudaFuncAttributeMaxDynamicSharedMemorySize, (int)smem1);
        cudaFuncSetAttribute(score_diag_kernel,
                             cudaFuncAttributeMaxDynamicSharedMemorySize, (int)smem2);
        cudaFuncSetAttribute(out_gemm_kernel,
                             cudaFuncAttributeMaxDynamicSharedMemorySize, (int)smem3);
        attr_done = true;
    }

    qkv_gemm_kernel<<<dim3(kC3 / 128, kRows / 128), 256, smem1>>>(x, Wqkv, bqkv);
    transpose_qk_kernel<<<2048, 256>>>();
    score_diag_kernel<<<dim3(kN / 128, kB * kH), 256, smem2>>>();
    out_gemm_kernel<<<dim3(kD / 128, kRows / 128, 4), 256, smem3>>>(W0);
    out_combine<<<1024, 256>>>(b0, out);
}

// round 9
// speedup vs baseline: 1.0765x; 1.0765x over previous
#include <cuda_runtime.h>
#include <cstdint>

// Problem constants
constexpr int kB = 4;
constexpr int kN = 1024;
constexpr int kD = 256;
constexpr int kH = 8;
constexpr int kDH  = kD * kH;          // 2048
constexpr int kNDH = kN * kDH;         // 2097152
constexpr int kSeg = kB * kNDH;        // 8388608  (q/k/v segment, floats)
constexpr int kC3  = 3 * kDH;          // 6144
constexpr int kRows = kB * kN;         // 4096

// Scratch (device globals; no dynamic allocation allowed)
__device__ float g_qkv[3ull * kSeg];   // ~100.7 MB : QKV in reference flat layout
__device__ float g_qkT[2ull * kSeg];   // ~64 MB : q(pre-scaled),k transposed [seg][bh][n][qd]
__device__ float g_diag[kRows * kH];
__device__ float g_part4[4][kRows * kD];  // k3 K-split partials

// ---------------- cp.async helpers ----------------
__device__ __forceinline__ void cp16(void* smem_dst, const void* gmem_src) {
    unsigned s = (unsigned)__cvta_generic_to_shared(smem_dst);
    asm volatile("cp.async.cg.shared.global [%0], [%1], 16;\n" :: "r"(s), "l"(gmem_src));
}
__device__ __forceinline__ void cp_commit() {
    asm volatile("cp.async.commit_group;\n");
}
template <int N>
__device__ __forceinline__ void cp_wait() {
    asm volatile("cp.async.wait_group %0;\n" :: "n"(N));
}

// ---------------- packed f32x2 helpers (Blackwell FFMA2) ----------------
__device__ __forceinline__ void ffma2(uint64_t& d, uint64_t a, uint64_t b) {
    asm("fma.rn.f32x2 %0, %1, %2, %0;" : "+l"(d) : "l"(a), "l"(b));
}
__device__ __forceinline__ uint64_t bcast2(float x) {
    uint64_t r;
    asm("mov.b64 %0, {%1, %1};" : "=l"(r) : "r"(__float_as_uint(x)));
    return r;
}
__device__ __forceinline__ float2 unpk2(uint64_t v) {
    uint32_t lo, hi;
    asm("mov.b64 {%0, %1}, %2;" : "=r"(lo), "=r"(hi) : "l"(v));
    return make_float2(__uint_as_float(lo), __uint_as_float(hi));
}

// ---------------------------------------------------------------------------
// Kernel 1: QKV = x @ Wqkv + bqkv     [4096,256] @ [256,6144]
// Round-2 proven staging; inner loop on packed FFMA2 (2 cols/reg).
// ---------------------------------------------------------------------------
__global__ __launch_bounds__(256, 2)
void qkv_gemm_kernel(const float* __restrict__ x,
                     const float* __restrict__ W,
                     const float* __restrict__ bias)
{
    extern __shared__ float sm[];
    float* As = sm;                    // [2][128][36]
    float* Bs = sm + 2 * 128 * 36;     // [2][32][132]

    const int t  = threadIdx.x;
    const int tx = t & 15, ty = t >> 4;
    const int r0 = blockIdx.y * 128;
    const int c0 = blockIdx.x * 128;

    const int af = t & 7,  am = t >> 3;
    const int bc = t & 31, bk = t >> 5;

    uint64_t acc[8][4] = {};   // [row][packed col pair]: jp0,1 -> cols tx*4+{01,23}; jp2,3 -> +64

#pragma unroll
    for (int i = 0; i < 4; i++) {
        int m = am + i * 32;
        cp16(&As[m * 36 + af * 4], &x[(size_t)(r0 + m) * kD + af * 4]);
    }
#pragma unroll
    for (int i = 0; i < 4; i++) {
        int k = bk + i * 8;
        cp16(&Bs[k * 132 + bc * 4], &W[(size_t)k * kC3 + c0 + bc * 4]);
    }
    cp_commit();

    for (int c = 0; c < 8; c++) {
        const int buf = c & 1;
        if (c < 7) {
            const int kc = (c + 1) * 32;
            const int nb = buf ^ 1;
#pragma unroll
            for (int i = 0; i < 4; i++) {
                int m = am + i * 32;
                cp16(&As[nb * 128 * 36 + m * 36 + af * 4],
                     &x[(size_t)(r0 + m) * kD + kc + af * 4]);
            }
#pragma unroll
            for (int i = 0; i < 4; i++) {
                int k = bk + i * 8;
                cp16(&Bs[nb * 32 * 132 + k * 132 + bc * 4],
                     &W[(size_t)(kc + k) * kC3 + c0 + bc * 4]);
            }
            cp_commit();
            cp_wait<1>();
        } else {
            cp_wait<0>();
        }
        __syncthreads();

        const float* A_ = &As[buf * 128 * 36];
        const float* B_ = &Bs[buf * 32 * 132];
#pragma unroll
        for (int kg = 0; kg < 32; kg += 4) {
            float4 av[8];
#pragma unroll
            for (int gi = 0; gi < 2; gi++)
#pragma unroll
                for (int i = 0; i < 4; i++)
                    av[gi * 4 + i] =
                        *(const float4*)&A_[(gi * 64 + ty * 4 + i) * 36 + kg];
#pragma unroll
            for (int kk = 0; kk < 4; kk++) {
                ulonglong2 p0 = *(const ulonglong2*)&B_[(kg + kk) * 132 + tx * 4];
                ulonglong2 p1 = *(const ulonglong2*)&B_[(kg + kk) * 132 + tx * 4 + 64];
#pragma unroll
                for (int r = 0; r < 8; r++) {
                    float a = (kk == 0) ? av[r].x : (kk == 1) ? av[r].y
                             : (kk == 2) ? av[r].z : av[r].w;
                    uint64_t ap = bcast2(a);
                    ffma2(acc[r][0], ap, p0.x);
                    ffma2(acc[r][1], ap, p0.y);
                    ffma2(acc[r][2], ap, p1.x);
                    ffma2(acc[r][3], ap, p1.y);
                }
            }
        }
        __syncthreads();
    }

#pragma unroll
    for (int gi = 0; gi < 2; gi++)
#pragma unroll
        for (int i = 0; i < 4; i++) {
            int r  = r0 + gi * 64 + ty * 4 + i;
            int rr = gi * 4 + i;
#pragma unroll
            for (int gj = 0; gj < 2; gj++) {
                int c = c0 + gj * 64 + tx * 4;
                float2 u0 = unpk2(acc[rr][gj * 2 + 0]);
                float2 u1 = unpk2(acc[rr][gj * 2 + 1]);
                float4 v;
                v.x = u0.x + bias[c + 0];
                v.y = u0.y + bias[c + 1];
                v.z = u1.x + bias[c + 2];
                v.w = u1.y + bias[c + 3];
                *(float4*)&g_qkv[(size_t)r * kC3 + c] = v;
            }
        }
}

// ---------------------------------------------------------------------------
// Transpose: q,k segments -> g_qkT[seg][b][h][n][qd]; q scaled by 1/16 here.
// ---------------------------------------------------------------------------
__global__ __launch_bounds__(256)
void transpose_qk_kernel()
{
    __shared__ float smt[8][32][33];   // [h][qd][n]
    const int bid = blockIdx.x;
    const int qb  = bid & 7;
    const int nb  = (bid >> 3) & 31;
    const int b   = (bid >> 8) & 3;
    const int seg = bid >> 10;
    const int t   = threadIdx.x;
    const float sc = (seg == 0) ? 0.0625f : 1.0f;

    const float* src = g_qkv + (size_t)seg * kSeg + (size_t)b * kNDH
                     + (size_t)(nb * 32) * kDH + qb * 32 * 8;
    {
        const int nl = t >> 3, f = t & 7;
        const int h0 = (f & 1) * 4, q0 = f >> 1;
#pragma unroll
        for (int i = 0; i < 8; i++) {
            float4 v = *(const float4*)&src[(size_t)nl * kDH + (f + i * 8) * 4];
            int ql = q0 + i * 4;
            smt[h0 + 0][ql][nl] = v.x;
            smt[h0 + 1][ql][nl] = v.y;
            smt[h0 + 2][ql][nl] = v.z;
            smt[h0 + 3][ql][nl] = v.w;
        }
    }
    __syncthreads();
    {
        const int q4 = (t & 7) * 4, hn = t >> 3;
#pragma unroll
        for (int i = 0; i < 8; i++) {
            int idx = hn + i * 32;
            int h = idx >> 5, n = idx & 31;
            float4 v;
            v.x = smt[h][q4 + 0][n] * sc;
            v.y = smt[h][q4 + 1][n] * sc;
            v.z = smt[h][q4 + 2][n] * sc;
            v.w = smt[h][q4 + 3][n] * sc;
            float* dst = g_qkT + (size_t)seg * kSeg
                       + (((size_t)(b * 8 + h) * kN + nb * 32 + n) * kD)
                       + qb * 32 + q4;
            *(float4*)dst = v;
        }
    }
}

// ---------------------------------------------------------------------------
// Kernel 2: per (b,h): S[m,n] = qs_m . k_n; column softmax over m (no max
// pass needed: |S| <~ 1); keep diagonal attn only. Packed FFMA2 inner loop,
// register colsum across all m-tiles, one final reduction.
// CTA: 128 n-cols, m swept in 8 tiles of 128. 256 threads, 8x8 microtile.
// ---------------------------------------------------------------------------
__global__ __launch_bounds__(256, 2)
void score_diag_kernel()
{
    extern __shared__ float sm[];
    float* As  = sm;                       // [2][128*36]
    float* Ks  = sm + 2 * 4608;            // [2][32*132]
    float* red = sm + 2 * 4608 + 2 * 4224; // [16*128]

    const int t  = threadIdx.x;
    const int tx = t & 15, ty = t >> 4;
    const int bh = blockIdx.y;
    const int b  = bh >> 3, h = bh & 7;
    const int n0 = blockIdx.x * 128;

    const float* Q  = g_qkT + (size_t)bh * (kN * kD);
    const float* Kp = g_qkT + (size_t)kSeg + (size_t)bh * (kN * kD);

    const int af = t & 7, am = t >> 3;   // A loader
    const int kq = t & 7, nl = t >> 3;   // K loader

    float colsum[8], dexp[8];
#pragma unroll
    for (int j = 0; j < 8; j++) { colsum[j] = 0.f; dexp[j] = 0.f; }

    for (int mt = 0; mt < 8; mt++) {
        const int m0 = mt * 128;
        uint64_t acc[8][4] = {};

        // preload chunk 0: A via cp.async, K into regs
        float4 kreg[4];
#pragma unroll
        for (int i = 0; i < 4; i++) {
            int m = am + i * 32;
            cp16(&As[m * 36 + af * 4], &Q[(size_t)(m0 + m) * kD + af * 4]);
        }
#pragma unroll
        for (int i = 0; i < 4; i++)
            kreg[i] = *(const float4*)&Kp[(size_t)(n0 + nl + 32 * i) * kD + kq * 4];
        cp_commit();

        for (int c = 0; c < 8; c++) {
            const int buf = c & 1;
            {
                float* kb_ = &Ks[buf * 4224];
#pragma unroll
                for (int i = 0; i < 4; i++) {
                    int n = nl + 32 * i;
                    kb_[(kq * 4 + 0) * 132 + n] = kreg[i].x;
                    kb_[(kq * 4 + 1) * 132 + n] = kreg[i].y;
                    kb_[(kq * 4 + 2) * 132 + n] = kreg[i].z;
                    kb_[(kq * 4 + 3) * 132 + n] = kreg[i].w;
                }
            }
            if (c < 7) {
                const int kc = (c + 1) * 32;
#pragma unroll
                for (int i = 0; i < 4; i++) {
                    int m = am + i * 32;
                    cp16(&As[(buf ^ 1) * 4608 + m * 36 + af * 4],
                         &Q[(size_t)(m0 + m) * kD + kc + af * 4]);
                }
                cp_commit();
#pragma unroll
                for (int i = 0; i < 4; i++)
                    kreg[i] = *(const float4*)
                        &Kp[(size_t)(n0 + nl + 32 * i) * kD + kc + kq * 4];
                cp_wait<1>();
            } else {
                cp_wait<0>();
            }
            __syncthreads();

            const float* A_ = &As[buf * 4608];
            const float* K_ = &Ks[buf * 4224];
#pragma unroll
            for (int kg = 0; kg < 32; kg += 4) {
                float4 av[8];
#pragma unroll
                for (int gi = 0; gi < 2; gi++)
#pragma unroll
                    for (int i = 0; i < 4; i++)
                        av[gi * 4 + i] =
                            *(const float4*)&A_[(gi * 64 + ty * 4 + i) * 36 + kg];
#pragma unroll
                for (int kk = 0; kk < 4; kk++) {
                    ulonglong2 p0 = *(const ulonglong2*)&K_[(kg + kk) * 132 + tx * 4];
                    ulonglong2 p1 = *(const ulonglong2*)&K_[(kg + kk) * 132 + tx * 4 + 64];
#pragma unroll
                    for (int r = 0; r < 8; r++) {
                        float a = (kk == 0) ? av[r].x : (kk == 1) ? av[r].y
                                 : (kk == 2) ? av[r].z : av[r].w;
                        uint64_t ap = bcast2(a);
                        ffma2(acc[r][0], ap, p0.x);
                        ffma2(acc[r][1], ap, p0.y);
                        ffma2(acc[r][2], ap, p1.x);
                        ffma2(acc[r][3], ap, p1.y);
                    }
                }
            }
            __syncthreads();
        }

        // ---- register-only epilogue ----
        // diagonal: global m == global n  <=>  mt == blockIdx.x, tx == ty, r == jj
        if (mt == blockIdx.x && tx == ty) {
#pragma unroll
            for (int j = 0; j < 8; j++) {
                int jp = ((j >> 2) << 1) | ((j & 3) >> 1);
                float2 u = unpk2(acc[j][jp]);
                dexp[j] = __expf((j & 1) ? u.y : u.x);
            }
        }
#pragma unroll
        for (int jp = 0; jp < 4; jp++) {
            float s0 = 0.f, s1 = 0.f;
#pragma unroll
            for (int r = 0; r < 8; r++) {
                float2 u = unpk2(acc[r][jp]);
                s0 += __expf(u.x);
                s1 += __expf(u.y);
            }
            int jj0 = ((jp >> 1) << 2) | ((jp & 1) << 1);
            colsum[jj0]     += s0;
            colsum[jj0 + 1] += s1;
        }
    }

    // ---- single final reduction across the 16 ty-groups ----
#pragma unroll
    for (int jj = 0; jj < 8; jj++) {
        int cl = (jj >> 2) * 64 + tx * 4 + (jj & 3);
        red[ty * 128 + cl] = colsum[jj];
    }
    __syncthreads();
    float total = 0.f;
    if (t < 128) {
        total = red[t];
#pragma unroll
        for (int r = 1; r < 16; r++) total += red[r * 128 + t];
    }
    __syncthreads();
#pragma unroll
    for (int jj = 0; jj < 8; jj++) {
        int cl = (jj >> 2) * 64 + tx * 4 + (jj & 3);
        red[ty * 128 + cl] = dexp[jj];
    }
    __syncthreads();
    if (t < 128) {
        float dv = red[t];
#pragma unroll
        for (int r = 1; r < 16; r++) dv += red[r * 128 + t];
        g_diag[((size_t)b * kN + (n0 + t)) * kH + h] = dv / total;
    }
}

// ---------------------------------------------------------------------------
// Kernel 3: partial = (diag .* v) @ W0, K-split 4.  [4096,2048]@[2048,256]
// grid(2 ctiles, 32 mtiles, 4 ksplit) = 256 CTAs. Packed FFMA2 inner loop.
// ---------------------------------------------------------------------------
__global__ __launch_bounds__(256, 2)
void out_gemm_kernel(const float* __restrict__ W0)
{
    extern __shared__ float sm[];
    float* As  = sm;                    // [2][128*36]
    float* Ws  = sm + 2 * 4608;         // [2][32*132]
    float* dsm = sm + 2 * 4608 + 2 * 4224;  // [128*8]

    const int t  = threadIdx.x;
    const int tx = t & 15, ty = t >> 4;
    const int c0 = blockIdx.x * 128;
    const int r0 = blockIdx.y * 128;
    const int kb = blockIdx.z * 512;
    const float* vseg = g_qkv + 2ull * kSeg;
    float* dst = g_part4[blockIdx.z];

    for (int idx = t; idx < 1024; idx += 256)
        dsm[idx] = g_diag[(size_t)(r0 + (idx >> 3)) * kH + (idx & 7)];

    const int af = t & 7,  am = t >> 3;   // A: f4 k-col af, rows am+32i
    const int bc = t & 31, bk = t >> 5;   // W: f4 col bc, k rows bk+8i

    uint64_t acc[8][4] = {};

    // preload chunk 0
    float4 areg[4];
#pragma unroll
    for (int i = 0; i < 4; i++) {
        int k = bk + i * 8;
        cp16(&Ws[k * 132 + bc * 4], &W0[(size_t)(kb + k) * kD + c0 + bc * 4]);
    }
    cp_commit();
#pragma unroll
    for (int i = 0; i < 4; i++) {
        int m = am + 32 * i;
        areg[i] = *(const float4*)&vseg[(size_t)(r0 + m) * kDH + kb + af * 4];
    }
    __syncthreads();   // dsm ready

    for (int c = 0; c < 16; c++) {
        const int buf = c & 1;
        {
            const int hoff = (af * 4) & 4;
#pragma unroll
            for (int i = 0; i < 4; i++) {
                int m = am + 32 * i;
                float4 dv = *(const float4*)&dsm[m * 8 + hoff];
                float4 v = areg[i];
                v.x *= dv.x; v.y *= dv.y; v.z *= dv.z; v.w *= dv.w;
                *(float4*)&As[buf * 4608 + m * 36 + af * 4] = v;
            }
        }
        if (c < 15) {
            const int kc = (c + 1) * 32;
#pragma unroll
            for (int i = 0; i < 4; i++) {
                int k = bk + i * 8;
                cp16(&Ws[(buf ^ 1) * 4224 + k * 132 + bc * 4],
                     &W0[(size_t)(kb + kc + k) * kD + c0 + bc * 4]);
            }
            cp_commit();
#pragma unroll
            for (int i = 0; i < 4; i++) {
                int m = am + 32 * i;
                areg[i] = *(const float4*)
                    &vseg[(size_t)(r0 + m) * kDH + kb + kc + af * 4];
            }
            cp_wait<1>();
        } else {
            cp_wait<0>();
        }
        __syncthreads();

        const float* A_ = &As[buf * 4608];
        const float* W_ = &Ws[buf * 4224];
#pragma unroll
        for (int kg = 0; kg < 32; kg += 4) {
            float4 av[8];
#pragma unroll
            for (int gi = 0; gi < 2; gi++)
#pragma unroll
                for (int i = 0; i < 4; i++)
                    av[gi * 4 + i] =
                        *(const float4*)&A_[(gi * 64 + ty * 4 + i) * 36 + kg];
#pragma unroll
            for (int kk = 0; kk < 4; kk++) {
                ulonglong2 p0 = *(const ulonglong2*)&W_[(kg + kk) * 132 + tx * 4];
                ulonglong2 p1 = *(const ulonglong2*)&W_[(kg + kk) * 132 + tx * 4 + 64];
#pragma unroll
                for (int r = 0; r < 8; r++) {
                    float a = (kk == 0) ? av[r].x : (kk == 1) ? av[r].y
                             : (kk == 2) ? av[r].z : av[r].w;
                    uint64_t ap = bcast2(a);
                    ffma2(acc[r][0], ap, p0.x);
                    ffma2(acc[r][1], ap, p0.y);
                    ffma2(acc[r][2], ap, p1.x);
                    ffma2(acc[r][3], ap, p1.y);
                }
            }
        }
        __syncthreads();
    }

#pragma unroll
    for (int gi = 0; gi < 2; gi++)
#pragma unroll
        for (int i = 0; i < 4; i++) {
            int r  = r0 + gi * 64 + ty * 4 + i;
            int rr = gi * 4 + i;
#pragma unroll
            for (int gj = 0; gj < 2; gj++) {
                int c = c0 + gj * 64 + tx * 4;
                float2 u0 = unpk2(acc[rr][gj * 2 + 0]);
                float2 u1 = unpk2(acc[rr][gj * 2 + 1]);
                float4 v;
                v.x = u0.x; v.y = u0.y; v.z = u1.x; v.w = u1.y;
                *(float4*)&dst[(size_t)r * kD + c] = v;
            }
        }
}

// ---------------------------------------------------------------------------
// Kernel 3b: out = sum of 4 partials + b0
// ---------------------------------------------------------------------------
__global__ __launch_bounds__(256)
void out_combine(const float* __restrict__ b0, float* __restrict__ out)
{
    int i4 = blockIdx.x * 256 + threadIdx.x;     // float4 index, 262144 total
    float4 a = *(const float4*)&g_part4[0][(size_t)i4 * 4];
    float4 b = *(const float4*)&g_part4[1][(size_t)i4 * 4];
    float4 c = *(const float4*)&g_part4[2][(size_t)i4 * 4];
    float4 d = *(const float4*)&g_part4[3][(size_t)i4 * 4];
    float4 bb = *(const float4*)&b0[(i4 & 63) * 4];
    float4 v;
    v.x = a.x + b.x + c.x + d.x + bb.x;
    v.y = a.y + b.y + c.y + d.y + bb.y;
    v.z = a.z + b.z + c.z + d.z + bb.z;
    v.w = a.w + b.w + c.w + d.w + bb.w;
    *(float4*)&out[(size_t)i4 * 4] = v;
}

// ---------------------------------------------------------------------------
extern "C" void kernel_launch(void* const* d_in, const int* in_sizes, int n_in,
                              void* d_out, int out_size)
{
    const float *x = nullptr, *Wqkv = nullptr, *bqkv = nullptr,
                *W0 = nullptr, *b0 = nullptr;
    for (int i = 0; i < n_in; i++) {
        switch (in_sizes[i]) {
            case kRows * kD: x    = (const float*)d_in[i]; break;
            case kD * kC3:   Wqkv = (const float*)d_in[i]; break;
            case kC3:        bqkv = (const float*)d_in[i]; break;
            case kDH * kD:   W0   = (const float*)d_in[i]; break;
            case kD:         b0   = (const float*)d_in[i]; break;
            default: break;
        }
    }
    float* out = (float*)d_out;

    const size_t smem1 = (size_t)(2 * 4608 + 2 * 4224) * sizeof(float);          // 70656
    const size_t smem2 = (size_t)(2 * 4608 + 2 * 4224 + 2048) * sizeof(float);   // 78848
    const size_t smem3 = (size_t)(2 * 4608 + 2 * 4224 + 1024) * sizeof(float);   // 74752
    static bool attr_done = false;
    if (!attr_done) {
        cudaFuncSetAttribute(qkv_gemm_kernel,
                             cudaFuncAttributeMaxDynamicSharedMemorySize, (int)smem1);
        cudaFuncSetAttribute(score_diag_kernel,
                             cudaFuncAttributeMaxDynamicSharedMemorySize, (int)smem2);
        cudaFuncSetAttribute(out_gemm_kernel,
                             cudaFuncAttributeMaxDynamicSharedMemorySize, (int)smem3);
        attr_done = true;
    }

    qkv_gemm_kernel<<<dim3(kC3 / 128, kRows / 128), 256, smem1>>>(x, Wqkv, bqkv);
    transpose_qk_kernel<<<2048, 256>>>();
    score_diag_kernel<<<dim3(kN / 128, kB * kH), 256, smem2>>>();
    out_gemm_kernel<<<dim3(kD / 128, kRows / 128, 4), 256, smem3>>>(W0);
    out_combine<<<1024, 256>>>(b0, out);
}